// round 1
// baseline (speedup 1.0000x reference)
#include <cuda_runtime.h>
#include <math.h>

// Problem constants
#define BZ    2
#define SEQ   1024
#define HID   4096
#define NHEAD 32
#define HDIM  128
#define IDIM  11008
#define MROWS 2048            // B*S

// ---------------------------------------------------------------------------
// Scratch (static device memory — no allocation anywhere)
// ---------------------------------------------------------------------------
__device__ float g_x   [(size_t)MROWS * HID];        // rmsnorm out (reused)
__device__ float g_qkv [(size_t)MROWS * 3 * HID];    // qkv (rope applied in place)
__device__ float g_attn[(size_t)MROWS * HID];        // attention out
__device__ float g_x2  [(size_t)MROWS * HID];        // residual after attention
__device__ float g_gu  [(size_t)MROWS * 2 * IDIM];   // gate/up
__device__ float g_mlp [(size_t)MROWS * IDIM];       // silu(gate)*up

// ---------------------------------------------------------------------------
// RMSNorm: one block per row of 4096
// ---------------------------------------------------------------------------
__global__ __launch_bounds__(256) void rmsnorm_kernel(const float* __restrict__ x,
                                                      const float* __restrict__ w,
                                                      float* __restrict__ out) {
    const size_t base = (size_t)blockIdx.x * HID;
    const float4* xr = (const float4*)(x + base);
    const float4* w4 = (const float4*)w;
    float4* orow = (float4*)(out + base);

    float4 v[4];
    float ss = 0.f;
#pragma unroll
    for (int it = 0; it < 4; it++) {
        v[it] = xr[threadIdx.x + 256 * it];
        ss += v[it].x * v[it].x + v[it].y * v[it].y + v[it].z * v[it].z + v[it].w * v[it].w;
    }
#pragma unroll
    for (int o = 16; o; o >>= 1) ss += __shfl_xor_sync(0xffffffffu, ss, o);

    __shared__ float warpsum[8];
    __shared__ float s_inv;
    const int lane = threadIdx.x & 31, wid = threadIdx.x >> 5;
    if (lane == 0) warpsum[wid] = ss;
    __syncthreads();
    if (threadIdx.x == 0) {
        float t = 0.f;
#pragma unroll
        for (int i = 0; i < 8; i++) t += warpsum[i];
        s_inv = rsqrtf(t * (1.0f / (float)HID) + 1e-6f);
    }
    __syncthreads();
    const float inv = s_inv;
#pragma unroll
    for (int it = 0; it < 4; it++) {
        float4 wv = w4[threadIdx.x + 256 * it];
        float4 r;
        r.x = v[it].x * inv * wv.x;
        r.y = v[it].y * inv * wv.y;
        r.z = v[it].z * inv * wv.z;
        r.w = v[it].w * inv * wv.w;
        orow[threadIdx.x + 256 * it] = r;
    }
}

// ---------------------------------------------------------------------------
// SGEMM: C[M,N] = A[M,K] @ B[K,N] (+ epilogue)
// EPI 0: none, 1: +bias[n], 2: +residual[m,n]
// Requires M%128==0, N%128==0, K%16==0 (holds for all shapes here).
// ---------------------------------------------------------------------------
template <int EPI>
__global__ __launch_bounds__(256, 2) void sgemm_kernel(const float* __restrict__ A,
                                                       const float* __restrict__ B,
                                                       const float* __restrict__ E,
                                                       float* __restrict__ C,
                                                       int M, int N, int K) {
    __shared__ float As[16 * 128];   // [k][m]
    __shared__ float Bs[16 * 128];   // [k][n]

    const int tid = threadIdx.x;
    const int bm = blockIdx.y * 128, bn = blockIdx.x * 128;
    const int arow = tid >> 2;             // 0..63 (and +64)
    const int acol = (tid & 3) * 4;        // k offset within tile
    const int brow = tid >> 5;             // 0..7 (and +8)
    const int bcol = (tid & 31) * 4;
    const int ty = tid >> 4, tx = tid & 15;

    float acc[8][8];
#pragma unroll
    for (int i = 0; i < 8; i++)
#pragma unroll
        for (int j = 0; j < 8; j++) acc[i][j] = 0.f;

    const float* Ap = A + (size_t)bm * K;

    for (int k0 = 0; k0 < K; k0 += 16) {
        const float4 a0 = *(const float4*)&Ap[(size_t)arow * K + k0 + acol];
        const float4 a1 = *(const float4*)&Ap[(size_t)(arow + 64) * K + k0 + acol];
        const float4 b0 = *(const float4*)&B[(size_t)(k0 + brow) * N + bn + bcol];
        const float4 b1 = *(const float4*)&B[(size_t)(k0 + brow + 8) * N + bn + bcol];
        __syncthreads();
        As[(acol + 0) * 128 + arow] = a0.x;
        As[(acol + 1) * 128 + arow] = a0.y;
        As[(acol + 2) * 128 + arow] = a0.z;
        As[(acol + 3) * 128 + arow] = a0.w;
        As[(acol + 0) * 128 + arow + 64] = a1.x;
        As[(acol + 1) * 128 + arow + 64] = a1.y;
        As[(acol + 2) * 128 + arow + 64] = a1.z;
        As[(acol + 3) * 128 + arow + 64] = a1.w;
        *(float4*)&Bs[brow * 128 + bcol] = b0;
        *(float4*)&Bs[(brow + 8) * 128 + bcol] = b1;
        __syncthreads();
#pragma unroll
        for (int k = 0; k < 16; k++) {
            const float4 aa0 = *(const float4*)&As[k * 128 + ty * 8];
            const float4 aa1 = *(const float4*)&As[k * 128 + ty * 8 + 4];
            const float4 bb0 = *(const float4*)&Bs[k * 128 + tx * 8];
            const float4 bb1 = *(const float4*)&Bs[k * 128 + tx * 8 + 4];
            const float ar[8] = {aa0.x, aa0.y, aa0.z, aa0.w, aa1.x, aa1.y, aa1.z, aa1.w};
            const float br[8] = {bb0.x, bb0.y, bb0.z, bb0.w, bb1.x, bb1.y, bb1.z, bb1.w};
#pragma unroll
            for (int i = 0; i < 8; i++)
#pragma unroll
                for (int j = 0; j < 8; j++) acc[i][j] += ar[i] * br[j];
        }
    }

#pragma unroll
    for (int i = 0; i < 8; i++) {
        const int row = bm + ty * 8 + i;
        const size_t off = (size_t)row * N + bn + tx * 8;
#pragma unroll
        for (int j = 0; j < 8; j++) {
            float v = acc[i][j];
            if (EPI == 1) v += E[bn + tx * 8 + j];
            if (EPI == 2) v += E[off + j];
            C[off + j] = v;
        }
    }
}

// ---------------------------------------------------------------------------
// RoPE in place on q,k inside qkv. grid (2048, 32), block 64 (one d in [0,64))
// ---------------------------------------------------------------------------
__global__ void rope_kernel(float* __restrict__ qkv, const int* __restrict__ positions) {
    const int row = blockIdx.x;        // b*S + s
    const int h = blockIdx.y;
    const int d = threadIdx.x;         // 0..63
    const float pos = (float)positions[row & (SEQ - 1)];
    const float freq = powf(10000.0f, -(float)d * (1.0f / 64.0f));
    float sn, cs;
    sincosf(pos * freq, &sn, &cs);

    float* qp = qkv + (size_t)row * (3 * HID) + h * HDIM;
    float* kp = qp + HID;
    const float q1 = qp[d], q2 = qp[d + 64];
    qp[d]      = q1 * cs - q2 * sn;
    qp[d + 64] = q2 * cs + q1 * sn;
    const float k1 = kp[d], k2 = kp[d + 64];
    kp[d]      = k1 * cs - k2 * sn;
    kp[d + 64] = k2 * cs + k1 * sn;
}

// ---------------------------------------------------------------------------
// Flash attention (fp32, causal). grid (16 qtiles, 32 heads, 2 batch), 256 thr.
// Each thread: row r = tid/4 of the 64-row Q tile, lane-slice cq = tid%4.
// ---------------------------------------------------------------------------
#define ATTN_SMEM ((64 * (128 + 132 + 128 + 65)) * 4)

__global__ __launch_bounds__(256) void attn_kernel(const float* __restrict__ qkv,
                                                   float* __restrict__ attn) {
    extern __shared__ float sm[];
    float* Qs = sm;                 // [64][128]
    float* Ks = Qs + 64 * 128;      // [64][132] padded
    float* Vs = Ks + 64 * 132;      // [64][128]
    float* Ps = Vs + 64 * 128;      // [64][65]  padded

    const int tid = threadIdx.x;
    const int qt = blockIdx.x, h = blockIdx.y, b = blockIdx.z;
    const int q0 = qt * 64;
    const size_t seqbase = (size_t)b * SEQ;
    const float scale = 0.08838834764831845f;   // 1/sqrt(128)

    for (int i = tid; i < 64 * 32; i += 256) {
        const int rr = i >> 5, c4 = (i & 31) << 2;
        float4 v = *(const float4*)&qkv[(seqbase + q0 + rr) * (3 * HID) + h * HDIM + c4];
        v.x *= scale; v.y *= scale; v.z *= scale; v.w *= scale;
        *(float4*)&Qs[rr * 128 + c4] = v;
    }

    const int r = tid >> 2, cq = tid & 3;
    float4 o4[8];
#pragma unroll
    for (int i = 0; i < 8; i++) o4[i] = make_float4(0.f, 0.f, 0.f, 0.f);
    float m = -1e30f, l = 0.f;

    for (int j = 0; j <= qt; j++) {
        const int k0 = j * 64;
        __syncthreads();   // previous PV done before overwriting K/V
        for (int i = tid; i < 64 * 32; i += 256) {
            const int rr = i >> 5, c4 = (i & 31) << 2;
            const size_t gb = (seqbase + k0 + rr) * (3 * HID) + h * HDIM + c4;
            *(float4*)&Ks[rr * 132 + c4] = *(const float4*)&qkv[gb + HID];
            *(float4*)&Vs[rr * 128 + c4] = *(const float4*)&qkv[gb + 2 * HID];
        }
        __syncthreads();

        // scores: thread covers cols c*4+cq, c=0..15
        float sv[16];
#pragma unroll
        for (int c = 0; c < 16; c++) sv[c] = 0.f;
        const float4* q4 = (const float4*)&Qs[r * 128];
        for (int d4 = 0; d4 < 32; d4++) {
            const float4 qv = q4[d4];
#pragma unroll
            for (int c = 0; c < 16; c++) {
                const float4 kv = *(const float4*)&Ks[(c * 4 + cq) * 132 + d4 * 4];
                sv[c] += qv.x * kv.x + qv.y * kv.y + qv.z * kv.z + qv.w * kv.w;
            }
        }
        if (j == qt) {
#pragma unroll
            for (int c = 0; c < 16; c++)
                if (k0 + c * 4 + cq > q0 + r) sv[c] = -1e30f;
        }

        float tmax = sv[0];
#pragma unroll
        for (int c = 1; c < 16; c++) tmax = fmaxf(tmax, sv[c]);
        tmax = fmaxf(tmax, __shfl_xor_sync(0xffffffffu, tmax, 1));
        tmax = fmaxf(tmax, __shfl_xor_sync(0xffffffffu, tmax, 2));
        const float mnew = fmaxf(m, tmax);
        const float corr = __expf(m - mnew);
        float psum = 0.f;
#pragma unroll
        for (int c = 0; c < 16; c++) {
            const float p = __expf(sv[c] - mnew);
            psum += p;
            Ps[r * 65 + c * 4 + cq] = p;
        }
        psum += __shfl_xor_sync(0xffffffffu, psum, 1);
        psum += __shfl_xor_sync(0xffffffffu, psum, 2);
        l = l * corr + psum;
        m = mnew;
#pragma unroll
        for (int i = 0; i < 8; i++) {
            o4[i].x *= corr; o4[i].y *= corr; o4[i].z *= corr; o4[i].w *= corr;
        }
        __syncwarp();   // Ps row written by the 4 same-warp lanes

        // PV: thread covers d = 16*i + 4*cq .. +3  (conflict-free)
        for (int k = 0; k < 64; k++) {
            const float p = Ps[r * 65 + k];
#pragma unroll
            for (int i = 0; i < 8; i++) {
                const float4 vv = *(const float4*)&Vs[k * 128 + i * 16 + cq * 4];
                o4[i].x += p * vv.x; o4[i].y += p * vv.y;
                o4[i].z += p * vv.z; o4[i].w += p * vv.w;
            }
        }
    }

    const float inv = 1.0f / l;
    const size_t ob = (seqbase + q0 + r) * HID + h * HDIM;
#pragma unroll
    for (int i = 0; i < 8; i++) {
        float4 v;
        v.x = o4[i].x * inv; v.y = o4[i].y * inv;
        v.z = o4[i].z * inv; v.w = o4[i].w * inv;
        *(float4*)&attn[ob + i * 16 + cq * 4] = v;
    }
}

// ---------------------------------------------------------------------------
// silu(gate) * up  (float4): 2048*2752 float4 == 22016 blocks * 256 threads
// ---------------------------------------------------------------------------
__global__ __launch_bounds__(256) void silu_mul_kernel(const float* __restrict__ gu,
                                                       float* __restrict__ out) {
    const size_t i = (size_t)blockIdx.x * 256 + threadIdx.x;   // float4 index
    const size_t mrow = i / (IDIM / 4);
    const size_t c4 = i % (IDIM / 4);
    const float4 g = *(const float4*)&gu[mrow * (2 * IDIM) + c4 * 4];
    const float4 u = *(const float4*)&gu[mrow * (2 * IDIM) + IDIM + c4 * 4];
    float4 r;
    r.x = g.x / (1.f + __expf(-g.x)) * u.x;
    r.y = g.y / (1.f + __expf(-g.y)) * u.y;
    r.z = g.z / (1.f + __expf(-g.z)) * u.z;
    r.w = g.w / (1.f + __expf(-g.w)) * u.w;
    *(float4*)&out[mrow * IDIM + c4 * 4] = r;
}

// ---------------------------------------------------------------------------
// Launch: 9 kernels on the default stream (graph-capturable, alloc-free)
// ---------------------------------------------------------------------------
extern "C" void kernel_launch(void* const* d_in, const int* in_sizes, int n_in,
                              void* d_out, int out_size) {
    const int*   positions = (const int*)  d_in[0];
    const float* hidden    = (const float*)d_in[1];
    const float* ln1       = (const float*)d_in[2];
    const float* ln2       = (const float*)d_in[3];
    const float* w_qkv     = (const float*)d_in[4];
    const float* b_qkv     = (const float*)d_in[5];
    const float* w_o       = (const float*)d_in[6];
    const float* w_gu      = (const float*)d_in[7];
    const float* w_down    = (const float*)d_in[8];
    float* out = (float*)d_out;

    void* p;
    cudaGetSymbolAddress(&p, g_x);    float* x    = (float*)p;
    cudaGetSymbolAddress(&p, g_qkv);  float* qkv  = (float*)p;
    cudaGetSymbolAddress(&p, g_attn); float* attn = (float*)p;
    cudaGetSymbolAddress(&p, g_x2);   float* x2   = (float*)p;
    cudaGetSymbolAddress(&p, g_gu);   float* gu   = (float*)p;
    cudaGetSymbolAddress(&p, g_mlp);  float* mlp  = (float*)p;

    cudaFuncSetAttribute(attn_kernel, cudaFuncAttributeMaxDynamicSharedMemorySize, ATTN_SMEM);

    // x = rmsnorm(hidden, ln1)
    rmsnorm_kernel<<<MROWS, 256>>>(hidden, ln1, x);
    // qkv = x @ w_qkv + b_qkv
    sgemm_kernel<1><<<dim3(12288 / 128, MROWS / 128), 256>>>(x, w_qkv, b_qkv, qkv,
                                                             MROWS, 3 * HID, HID);
    // rope(q), rope(k) in place
    rope_kernel<<<dim3(MROWS, NHEAD), 64>>>(qkv, positions);
    // attn = softmax(q k^T / sqrt(d), causal) @ v
    attn_kernel<<<dim3(SEQ / 64, NHEAD, BZ), 256, ATTN_SMEM>>>(qkv, attn);
    // x2 = hidden + attn @ w_o
    sgemm_kernel<2><<<dim3(HID / 128, MROWS / 128), 256>>>(attn, w_o, hidden, x2,
                                                           MROWS, HID, HID);
    // x = rmsnorm(x2, ln2)
    rmsnorm_kernel<<<MROWS, 256>>>(x2, ln2, x);
    // gu = x @ w_gate_up
    sgemm_kernel<0><<<dim3(2 * IDIM / 128, MROWS / 128), 256>>>(x, w_gu, nullptr, gu,
                                                                MROWS, 2 * IDIM, HID);
    // mlp = silu(gate) * up
    silu_mul_kernel<<<(MROWS * (IDIM / 4)) / 256, 256>>>(gu, mlp);
    // out = x2 + mlp @ w_down
    sgemm_kernel<2><<<dim3(HID / 128, MROWS / 128), 256>>>(mlp, w_down, x2, out,
                                                           MROWS, HID, IDIM);
}

// round 3
// speedup vs baseline: 1.9691x; 1.9691x over previous
#include <cuda_runtime.h>
#include <cstdint>
#include <math.h>

// Problem constants
#define BZ    2
#define SEQ   1024
#define HID   4096
#define NHEAD 32
#define HDIM  128
#define IDIM  11008
#define MROWS 2048            // B*S

// ===========================================================================
// Scratch (static device memory — no allocation anywhere)
// ===========================================================================
__device__ float g_x   [(size_t)MROWS * HID];
__device__ float g_qkv [(size_t)MROWS * 3 * HID];
__device__ float g_attn[(size_t)MROWS * HID];
__device__ float g_x2  [(size_t)MROWS * HID];
__device__ float g_gu  [(size_t)MROWS * 2 * IDIM];
__device__ float g_mlp [(size_t)MROWS * IDIM];
// Transposed (tf32-rounded) weights: qkvT | oT | guT | downT
#define WT_QKV 0
#define WT_O   ((size_t)3 * HID * HID)
#define WT_GU  (WT_O + (size_t)HID * HID)
#define WT_DN  (WT_GU + (size_t)HID * 2 * IDIM)
#define WT_TOT (WT_DN + (size_t)HID * IDIM)
__device__ float g_wT[WT_TOT];

__device__ __forceinline__ float tf32r(float x) {
    uint32_t u;
    asm("cvt.rna.tf32.f32 %0, %1;" : "=r"(u) : "f"(x));
    return __uint_as_float(u);
}

// mma.sync m16n8k4 tf32 (base PTX, valid on sm_103 non-'a' target)
__device__ __forceinline__ void mma_tf32_k4(float* c, uint32_t a0, uint32_t a1, uint32_t b0) {
    asm volatile("mma.sync.aligned.m16n8k4.row.col.f32.tf32.tf32.f32 "
                 "{%0,%1,%2,%3}, {%4,%5}, {%6}, {%0,%1,%2,%3};"
                 : "+f"(c[0]), "+f"(c[1]), "+f"(c[2]), "+f"(c[3])
                 : "r"(a0), "r"(a1), "r"(b0));
}

// ===========================================================================
// Weight transpose + tf32 rounding: src [K][N] -> dst [N][K]
// ===========================================================================
__global__ __launch_bounds__(256) void transpose_tf32_kernel(const float* __restrict__ src,
                                                             float* __restrict__ dst,
                                                             int K, int N) {
    __shared__ float tile[32][33];
    const int bx = blockIdx.x * 32;   // n
    const int by = blockIdx.y * 32;   // k
    const int tx = threadIdx.x & 31, ty = threadIdx.x >> 5;  // 32 x 8
#pragma unroll
    for (int j = 0; j < 32; j += 8)
        tile[ty + j][tx] = tf32r(src[(size_t)(by + ty + j) * N + bx + tx]);
    __syncthreads();
#pragma unroll
    for (int j = 0; j < 32; j += 8)
        dst[(size_t)(bx + ty + j) * K + by + tx] = tile[tx][ty + j];
}

// ===========================================================================
// Tensor-core tf32 GEMM via mma.sync: C[M,N] = A[M,K] @ BT[N,K]^T (+ epilogue)
// EPI 0: none, 1: +bias[n], 2: +residual[m,n]
// BM=128, BN=128, BK=16, 256 threads, 8 warps (warp tile 32x64).
// Smem rows padded to 20 words: fragment LDS banks (20g + t) are conflict-free
// and float4 STS stays 16B-aligned.
// ===========================================================================
#define GBM 128
#define GBN 128
#define GBK 16
#define PITCH 20
#define TILE_W (GBM * PITCH)   // 2560 floats per buffer per matrix

template <int EPI>
__global__ __launch_bounds__(256, 2) void mma_gemm_kernel(const float* __restrict__ A,
                                                          const float* __restrict__ BT,
                                                          const float* __restrict__ E,
                                                          float* __restrict__ C,
                                                          int M, int N, int K) {
    __shared__ float sA[2 * TILE_W];
    __shared__ float sB[2 * TILE_W];

    const int tid = threadIdx.x;
    const int bm = blockIdx.y * GBM;
    const int bn = blockIdx.x * GBN;
    const int w = tid >> 5, lane = tid & 31;
    const int g = lane >> 2, t = lane & 3;
    const int wm = w & 3;          // 4 warps over M (32 rows each)
    const int wn = w >> 2;         // 2 warps over N (64 cols each)

    const float* Ap = A + (size_t)bm * K;
    const float* Bp = BT + (size_t)bn * K;
    const int NS = K / GBK;

    // global load indices: 512 float4 per matrix per stage, 2 per thread
    const int r0 = (tid + 0) >> 2,   q0 = (tid + 0) & 3;
    const int r1 = (tid + 256) >> 2, q1 = (tid + 256) & 3;

    float acc[2][8][4];
#pragma unroll
    for (int mt = 0; mt < 2; mt++)
#pragma unroll
        for (int nt = 0; nt < 8; nt++)
#pragma unroll
            for (int i = 0; i < 4; i++) acc[mt][nt][i] = 0.f;

    // ---- prologue: stage 0 ----
    {
        float4 a0 = *(const float4*)&Ap[(size_t)r0 * K + q0 * 4];
        float4 a1 = *(const float4*)&Ap[(size_t)r1 * K + q1 * 4];
        float4 b0 = *(const float4*)&Bp[(size_t)r0 * K + q0 * 4];
        float4 b1 = *(const float4*)&Bp[(size_t)r1 * K + q1 * 4];
        a0.x = tf32r(a0.x); a0.y = tf32r(a0.y); a0.z = tf32r(a0.z); a0.w = tf32r(a0.w);
        a1.x = tf32r(a1.x); a1.y = tf32r(a1.y); a1.z = tf32r(a1.z); a1.w = tf32r(a1.w);
        *(float4*)&sA[r0 * PITCH + q0 * 4] = a0;
        *(float4*)&sA[r1 * PITCH + q1 * 4] = a1;
        *(float4*)&sB[r0 * PITCH + q0 * 4] = b0;
        *(float4*)&sB[r1 * PITCH + q1 * 4] = b1;
    }
    __syncthreads();

    for (int s = 0; s < NS; s++) {
        const int buf = s & 1;
        float4 a0, a1, b0, b1;
        if (s + 1 < NS) {
            const int k0 = (s + 1) * GBK;
            a0 = *(const float4*)&Ap[(size_t)r0 * K + k0 + q0 * 4];
            a1 = *(const float4*)&Ap[(size_t)r1 * K + k0 + q1 * 4];
            b0 = *(const float4*)&Bp[(size_t)r0 * K + k0 + q0 * 4];
            b1 = *(const float4*)&Bp[(size_t)r1 * K + k0 + q1 * 4];
        }

        const float* As = sA + buf * TILE_W;
        const float* Bs = sB + buf * TILE_W;
#pragma unroll
        for (int ks = 0; ks < 4; ks++) {
            const int kk = ks * 4 + t;
            uint32_t afr[2][2], bfr[8];
#pragma unroll
            for (int mt = 0; mt < 2; mt++) {
                const int mrow = wm * 32 + mt * 16 + g;
                afr[mt][0] = __float_as_uint(As[mrow * PITCH + kk]);
                afr[mt][1] = __float_as_uint(As[(mrow + 8) * PITCH + kk]);
            }
#pragma unroll
            for (int nt = 0; nt < 8; nt++)
                bfr[nt] = __float_as_uint(Bs[(wn * 64 + nt * 8 + g) * PITCH + kk]);
#pragma unroll
            for (int mt = 0; mt < 2; mt++)
#pragma unroll
                for (int nt = 0; nt < 8; nt++)
                    mma_tf32_k4(acc[mt][nt], afr[mt][0], afr[mt][1], bfr[nt]);
        }

        if (s + 1 < NS) {
            float* dA = sA + (buf ^ 1) * TILE_W;
            float* dB = sB + (buf ^ 1) * TILE_W;
            a0.x = tf32r(a0.x); a0.y = tf32r(a0.y); a0.z = tf32r(a0.z); a0.w = tf32r(a0.w);
            a1.x = tf32r(a1.x); a1.y = tf32r(a1.y); a1.z = tf32r(a1.z); a1.w = tf32r(a1.w);
            *(float4*)&dA[r0 * PITCH + q0 * 4] = a0;
            *(float4*)&dA[r1 * PITCH + q1 * 4] = a1;
            *(float4*)&dB[r0 * PITCH + q0 * 4] = b0;
            *(float4*)&dB[r1 * PITCH + q1 * 4] = b1;
        }
        __syncthreads();
    }

    // ---- epilogue ----
#pragma unroll
    for (int mt = 0; mt < 2; mt++) {
        const int row0 = bm + wm * 32 + mt * 16 + g;
#pragma unroll
        for (int nt = 0; nt < 8; nt++) {
            const int col = bn + wn * 64 + nt * 8 + 2 * t;
            float2 v0 = make_float2(acc[mt][nt][0], acc[mt][nt][1]);
            float2 v1 = make_float2(acc[mt][nt][2], acc[mt][nt][3]);
            if (EPI == 1) {
                const float2 e = *(const float2*)&E[col];
                v0.x += e.x; v0.y += e.y; v1.x += e.x; v1.y += e.y;
            }
            if (EPI == 2) {
                const float2 e0 = *(const float2*)&E[(size_t)row0 * N + col];
                const float2 e1 = *(const float2*)&E[(size_t)(row0 + 8) * N + col];
                v0.x += e0.x; v0.y += e0.y; v1.x += e1.x; v1.y += e1.y;
            }
            *(float2*)&C[(size_t)row0 * N + col] = v0;
            *(float2*)&C[(size_t)(row0 + 8) * N + col] = v1;
        }
    }
}

// ===========================================================================
// RMSNorm
// ===========================================================================
__global__ __launch_bounds__(256) void rmsnorm_kernel(const float* __restrict__ x,
                                                      const float* __restrict__ w,
                                                      float* __restrict__ out) {
    const size_t base = (size_t)blockIdx.x * HID;
    const float4* xr = (const float4*)(x + base);
    const float4* w4 = (const float4*)w;
    float4* orow = (float4*)(out + base);

    float4 v[4];
    float ss = 0.f;
#pragma unroll
    for (int it = 0; it < 4; it++) {
        v[it] = xr[threadIdx.x + 256 * it];
        ss += v[it].x * v[it].x + v[it].y * v[it].y + v[it].z * v[it].z + v[it].w * v[it].w;
    }
#pragma unroll
    for (int o = 16; o; o >>= 1) ss += __shfl_xor_sync(0xffffffffu, ss, o);

    __shared__ float warpsum[8];
    __shared__ float s_inv;
    const int lane = threadIdx.x & 31, wid = threadIdx.x >> 5;
    if (lane == 0) warpsum[wid] = ss;
    __syncthreads();
    if (threadIdx.x == 0) {
        float tsum = 0.f;
#pragma unroll
        for (int i = 0; i < 8; i++) tsum += warpsum[i];
        s_inv = rsqrtf(tsum * (1.0f / (float)HID) + 1e-6f);
    }
    __syncthreads();
    const float inv = s_inv;
#pragma unroll
    for (int it = 0; it < 4; it++) {
        float4 wv = w4[threadIdx.x + 256 * it];
        float4 r;
        r.x = v[it].x * inv * wv.x;
        r.y = v[it].y * inv * wv.y;
        r.z = v[it].z * inv * wv.z;
        r.w = v[it].w * inv * wv.w;
        orow[threadIdx.x + 256 * it] = r;
    }
}

// ===========================================================================
// RoPE in place on q,k inside qkv
// ===========================================================================
__global__ void rope_kernel(float* __restrict__ qkv, const int* __restrict__ positions) {
    const int row = blockIdx.x;
    const int h = blockIdx.y;
    const int d = threadIdx.x;   // 0..63
    const float pos = (float)positions[row & (SEQ - 1)];
    const float freq = powf(10000.0f, -(float)d * (1.0f / 64.0f));
    float sn, cs;
    sincosf(pos * freq, &sn, &cs);

    float* qp = qkv + (size_t)row * (3 * HID) + h * HDIM;
    float* kp = qp + HID;
    const float q1 = qp[d], q2 = qp[d + 64];
    qp[d]      = q1 * cs - q2 * sn;
    qp[d + 64] = q2 * cs + q1 * sn;
    const float k1 = kp[d], k2 = kp[d + 64];
    kp[d]      = k1 * cs - k2 * sn;
    kp[d + 64] = k2 * cs + k1 * sn;
}

// ===========================================================================
// Flash attention (fp32, causal)
// ===========================================================================
#define ATTN_SMEM ((64 * (128 + 132 + 128 + 65)) * 4)

__global__ __launch_bounds__(256) void attn_kernel(const float* __restrict__ qkv,
                                                   float* __restrict__ attn) {
    extern __shared__ float sm[];
    float* Qs = sm;
    float* Ks = Qs + 64 * 128;
    float* Vs = Ks + 64 * 132;
    float* Ps = Vs + 64 * 128;

    const int tid = threadIdx.x;
    const int qt = blockIdx.x, h = blockIdx.y, b = blockIdx.z;
    const int q0 = qt * 64;
    const size_t seqbase = (size_t)b * SEQ;
    const float scale = 0.08838834764831845f;

    for (int i = tid; i < 64 * 32; i += 256) {
        const int rr = i >> 5, c4 = (i & 31) << 2;
        float4 v = *(const float4*)&qkv[(seqbase + q0 + rr) * (3 * HID) + h * HDIM + c4];
        v.x *= scale; v.y *= scale; v.z *= scale; v.w *= scale;
        *(float4*)&Qs[rr * 128 + c4] = v;
    }

    const int r = tid >> 2, cq = tid & 3;
    float4 o4[8];
#pragma unroll
    for (int i = 0; i < 8; i++) o4[i] = make_float4(0.f, 0.f, 0.f, 0.f);
    float m = -1e30f, l = 0.f;

    for (int j = 0; j <= qt; j++) {
        const int k0 = j * 64;
        __syncthreads();
        for (int i = tid; i < 64 * 32; i += 256) {
            const int rr = i >> 5, c4 = (i & 31) << 2;
            const size_t gb = (seqbase + k0 + rr) * (3 * HID) + h * HDIM + c4;
            *(float4*)&Ks[rr * 132 + c4] = *(const float4*)&qkv[gb + HID];
            *(float4*)&Vs[rr * 128 + c4] = *(const float4*)&qkv[gb + 2 * HID];
        }
        __syncthreads();

        float sv[16];
#pragma unroll
        for (int c = 0; c < 16; c++) sv[c] = 0.f;
        const float4* q4 = (const float4*)&Qs[r * 128];
        for (int d4 = 0; d4 < 32; d4++) {
            const float4 qv = q4[d4];
#pragma unroll
            for (int c = 0; c < 16; c++) {
                const float4 kv = *(const float4*)&Ks[(c * 4 + cq) * 132 + d4 * 4];
                sv[c] += qv.x * kv.x + qv.y * kv.y + qv.z * kv.z + qv.w * kv.w;
            }
        }
        if (j == qt) {
#pragma unroll
            for (int c = 0; c < 16; c++)
                if (k0 + c * 4 + cq > q0 + r) sv[c] = -1e30f;
        }

        float tmax = sv[0];
#pragma unroll
        for (int c = 1; c < 16; c++) tmax = fmaxf(tmax, sv[c]);
        tmax = fmaxf(tmax, __shfl_xor_sync(0xffffffffu, tmax, 1));
        tmax = fmaxf(tmax, __shfl_xor_sync(0xffffffffu, tmax, 2));
        const float mnew = fmaxf(m, tmax);
        const float corr = __expf(m - mnew);
        float psum = 0.f;
#pragma unroll
        for (int c = 0; c < 16; c++) {
            const float p = __expf(sv[c] - mnew);
            psum += p;
            Ps[r * 65 + c * 4 + cq] = p;
        }
        psum += __shfl_xor_sync(0xffffffffu, psum, 1);
        psum += __shfl_xor_sync(0xffffffffu, psum, 2);
        l = l * corr + psum;
        m = mnew;
#pragma unroll
        for (int i = 0; i < 8; i++) {
            o4[i].x *= corr; o4[i].y *= corr; o4[i].z *= corr; o4[i].w *= corr;
        }
        __syncwarp();

        for (int k = 0; k < 64; k++) {
            const float p = Ps[r * 65 + k];
#pragma unroll
            for (int i = 0; i < 8; i++) {
                const float4 vv = *(const float4*)&Vs[k * 128 + i * 16 + cq * 4];
                o4[i].x += p * vv.x; o4[i].y += p * vv.y;
                o4[i].z += p * vv.z; o4[i].w += p * vv.w;
            }
        }
    }

    const float inv = 1.0f / l;
    const size_t ob = (seqbase + q0 + r) * HID + h * HDIM;
#pragma unroll
    for (int i = 0; i < 8; i++) {
        float4 v;
        v.x = o4[i].x * inv; v.y = o4[i].y * inv;
        v.z = o4[i].z * inv; v.w = o4[i].w * inv;
        *(float4*)&attn[ob + i * 16 + cq * 4] = v;
    }
}

// ===========================================================================
// silu(gate) * up
// ===========================================================================
__global__ __launch_bounds__(256) void silu_mul_kernel(const float* __restrict__ gu,
                                                       float* __restrict__ out) {
    const size_t i = (size_t)blockIdx.x * 256 + threadIdx.x;
    const size_t mrow = i / (IDIM / 4);
    const size_t c4 = i % (IDIM / 4);
    const float4 g = *(const float4*)&gu[mrow * (2 * IDIM) + c4 * 4];
    const float4 u = *(const float4*)&gu[mrow * (2 * IDIM) + IDIM + c4 * 4];
    float4 r;
    r.x = g.x / (1.f + __expf(-g.x)) * u.x;
    r.y = g.y / (1.f + __expf(-g.y)) * u.y;
    r.z = g.z / (1.f + __expf(-g.z)) * u.z;
    r.w = g.w / (1.f + __expf(-g.w)) * u.w;
    *(float4*)&out[mrow * IDIM + c4 * 4] = r;
}

// ===========================================================================
// Launch
// ===========================================================================
extern "C" void kernel_launch(void* const* d_in, const int* in_sizes, int n_in,
                              void* d_out, int out_size) {
    const int*   positions = (const int*)  d_in[0];
    const float* hidden    = (const float*)d_in[1];
    const float* ln1       = (const float*)d_in[2];
    const float* ln2       = (const float*)d_in[3];
    const float* w_qkv     = (const float*)d_in[4];
    const float* b_qkv     = (const float*)d_in[5];
    const float* w_o       = (const float*)d_in[6];
    const float* w_gu      = (const float*)d_in[7];
    const float* w_down    = (const float*)d_in[8];
    float* out = (float*)d_out;

    void* p;
    cudaGetSymbolAddress(&p, g_x);    float* x    = (float*)p;
    cudaGetSymbolAddress(&p, g_qkv);  float* qkv  = (float*)p;
    cudaGetSymbolAddress(&p, g_attn); float* attn = (float*)p;
    cudaGetSymbolAddress(&p, g_x2);   float* x2   = (float*)p;
    cudaGetSymbolAddress(&p, g_gu);   float* gu   = (float*)p;
    cudaGetSymbolAddress(&p, g_mlp);  float* mlp  = (float*)p;
    cudaGetSymbolAddress(&p, g_wT);   float* wT   = (float*)p;
    float* qkvT = wT + WT_QKV;
    float* oT   = wT + WT_O;
    float* guT  = wT + WT_GU;
    float* dnT  = wT + WT_DN;

    cudaFuncSetAttribute(attn_kernel, cudaFuncAttributeMaxDynamicSharedMemorySize, ATTN_SMEM);

    // Weight transposes (+ tf32 rounding)
    transpose_tf32_kernel<<<dim3((3 * HID) / 32, HID / 32), 256>>>(w_qkv, qkvT, HID, 3 * HID);
    transpose_tf32_kernel<<<dim3(HID / 32, HID / 32), 256>>>(w_o, oT, HID, HID);
    transpose_tf32_kernel<<<dim3((2 * IDIM) / 32, HID / 32), 256>>>(w_gu, guT, HID, 2 * IDIM);
    transpose_tf32_kernel<<<dim3(HID / 32, IDIM / 32), 256>>>(w_down, dnT, IDIM, HID);

    // x = rmsnorm(hidden, ln1)
    rmsnorm_kernel<<<MROWS, 256>>>(hidden, ln1, x);
    // qkv = x @ w_qkv + b_qkv
    mma_gemm_kernel<1><<<dim3((3 * HID) / GBN, MROWS / GBM), 256>>>(
        x, qkvT, b_qkv, qkv, MROWS, 3 * HID, HID);
    // rope
    rope_kernel<<<dim3(MROWS, NHEAD), 64>>>(qkv, positions);
    // attention
    attn_kernel<<<dim3(SEQ / 64, NHEAD, BZ), 256, ATTN_SMEM>>>(qkv, attn);
    // x2 = hidden + attn @ w_o
    mma_gemm_kernel<2><<<dim3(HID / GBN, MROWS / GBM), 256>>>(
        attn, oT, hidden, x2, MROWS, HID, HID);
    // x = rmsnorm(x2, ln2)
    rmsnorm_kernel<<<MROWS, 256>>>(x2, ln2, x);
    // gu = x @ w_gate_up
    mma_gemm_kernel<0><<<dim3((2 * IDIM) / GBN, MROWS / GBM), 256>>>(
        x, guT, nullptr, gu, MROWS, 2 * IDIM, HID);
    // mlp = silu(gate) * up
    silu_mul_kernel<<<(MROWS * (IDIM / 4)) / 256, 256>>>(gu, mlp);
    // out = x2 + mlp @ w_down
    mma_gemm_kernel<2><<<dim3(HID / GBN, MROWS / GBM), 256>>>(
        mlp, dnT, x2, out, MROWS, HID, IDIM);
}